// round 16
// baseline (speedup 1.0000x reference)
#include <cuda_runtime.h>
#include <cstdint>

#define NN     25
#define GPBK   16              // graphs per block
#define THREADS 448            // 400 compute threads in phase 1
#define LW     12              // fused row: [L0..8 | x,y,z]; 48B, 16B-aligned
#define GROW   (NN * LW)       // 300 floats per graph in s_L

struct A9 { float R[9]; float p[3]; };

__device__ __forceinline__ uint32_t smem_u32(const void* p) {
    return (uint32_t)__cvta_generic_to_shared(p);
}

__device__ __forceinline__ A9 load_row(const float* __restrict__ row) {
    const float4* rp = (const float4*)row;
    const float4 a = rp[0], b = rp[1], c = rp[2];
    A9 o;
    o.R[0]=a.x; o.R[1]=a.y; o.R[2]=a.z; o.R[3]=a.w; o.R[4]=b.x; o.R[5]=b.y;
    o.R[6]=b.z; o.R[7]=b.w; o.R[8]=c.x; o.p[0]=c.y; o.p[1]=c.z; o.p[2]=c.w;
    return o;
}

// W = W ∘ (L, xyz):  p += R*xyz ; R = R*L
__device__ __forceinline__ void step(A9& W, const float* __restrict__ Lrow) {
    const float4* lp = (const float4*)Lrow;
    const float4 LA = lp[0], LB = lp[1], LC = lp[2];
    W.p[0] += W.R[0]*LC.y + W.R[1]*LC.z + W.R[2]*LC.w;
    W.p[1] += W.R[3]*LC.y + W.R[4]*LC.z + W.R[5]*LC.w;
    W.p[2] += W.R[6]*LC.y + W.R[7]*LC.z + W.R[8]*LC.w;
    const float n0 = W.R[0]*LA.x + W.R[1]*LA.w + W.R[2]*LB.z;
    const float n1 = W.R[0]*LA.y + W.R[1]*LB.x + W.R[2]*LB.w;
    const float n2 = W.R[0]*LA.z + W.R[1]*LB.y + W.R[2]*LC.x;
    const float n3 = W.R[3]*LA.x + W.R[4]*LA.w + W.R[5]*LB.z;
    const float n4 = W.R[3]*LA.y + W.R[4]*LB.x + W.R[5]*LB.w;
    const float n5 = W.R[3]*LA.z + W.R[4]*LB.y + W.R[5]*LC.x;
    const float n6 = W.R[6]*LA.x + W.R[7]*LA.w + W.R[8]*LB.z;
    const float n7 = W.R[6]*LA.y + W.R[7]*LB.x + W.R[8]*LB.w;
    const float n8 = W.R[6]*LA.z + W.R[7]*LB.y + W.R[8]*LC.x;
    W.R[0]=n0; W.R[1]=n1; W.R[2]=n2; W.R[3]=n3; W.R[4]=n4;
    W.R[5]=n5; W.R[6]=n6; W.R[7]=n7; W.R[8]=n8;
}

__device__ __forceinline__ void store_w(float* __restrict__ row, const A9& W) {
    float4* rp = (float4*)row;
    rp[0] = make_float4(W.R[0], W.R[1], W.R[2], W.R[3]);
    rp[1] = make_float4(W.R[4], W.R[5], W.R[6], W.R[7]);
    rp[2] = make_float4(W.R[8], W.p[0], W.p[1], W.p[2]);
}

__device__ __forceinline__ void stage_out(int r, const A9& W,
    float rx, float ry, float rz,
    float* __restrict__ s_pos, float* __restrict__ s_gps, float* __restrict__ s_rot)
{
    float* sp = s_pos + r*3;
    float* sg = s_gps + r*3;
    float* sr = s_rot + r*9;
    sp[0]=W.p[0]; sp[1]=W.p[1]; sp[2]=W.p[2];
    sg[0]=W.p[0]+rx; sg[1]=W.p[1]+ry; sg[2]=W.p[2]+rz;
    #pragma unroll
    for (int k=0;k<9;k++) sr[k]=W.R[k];
}

__device__ __forceinline__ void mbar_wait0(uint32_t mb) {
    uint32_t done;
    asm volatile(
        "{\n\t.reg .pred p;\n\t"
        "mbarrier.try_wait.parity.acquire.cta.shared::cta.b64 p, [%1], %2, 0x989680;\n\t"
        "selp.b32 %0, 1, 0, p;\n\t}"
        : "=r"(done) : "r"(mb), "r"(0) : "memory");
    while (!done) {
        asm volatile(
            "{\n\t.reg .pred p;\n\t"
            "mbarrier.try_wait.parity.acquire.cta.shared::cta.b64 p, [%1], %2, 0x989680;\n\t"
            "selp.b32 %0, 1, 0, p;\n\t}"
            : "=r"(done) : "r"(mb), "r"(0) : "memory");
    }
}

__global__ void __launch_bounds__(THREADS, 4)
fk_kernel(const float* __restrict__ x,
          const float* __restrict__ off,
          const float* __restrict__ axis,
          float* __restrict__ out_pos,
          float* __restrict__ out_rot,
          float* __restrict__ out_gpos,
          int G)
{
    // s_out = [ pos (1200) | gps (1200) | rot (3600) ] floats, output layout.
    // Input offsets (2400 floats) are TMA'd into the rot region and consumed
    // in phase 1; output writes happen only after the phase-1 barrier.
    __shared__ __align__(16) float s_L  [GPBK * GROW];     // 19200B
    __shared__ __align__(16) float s_out[GPBK * 375];      // 24000B
    __shared__ __align__(16) float s_W  [GPBK * 4 * LW];   // 3072B (nodes 3..6)
    __shared__ float4 s_ax[NN];
    __shared__ __align__(8) unsigned long long s_mb;

    float* s_pos = s_out;
    float* s_gps = s_out + GPBK * 75;
    float* s_rot = s_out + GPBK * 150;
    float* s_off = s_rot;                   // alias: inputs live here pre-barrier

    const int t  = threadIdx.x;
    const int g0 = blockIdx.x * GPBK;
    const int ng = min(GPBK, G - g0);
    const int NT = ng * NN;
    const bool full = (ng == GPBK);

    if (t == 0) {
        const uint32_t mb = smem_u32(&s_mb);
        asm volatile("mbarrier.init.shared.b64 [%0], %1;" :: "r"(mb), "r"(1) : "memory");
    }
    if (t < NN) {
        const float a0 = axis[t*3+0], a1 = axis[t*3+1], a2 = axis[t*3+2];
        s_ax[t] = make_float4(a0, a1, a2, sqrtf(a0*a0 + a1*a1 + a2*a2));
    }
    __syncthreads();

    // ---- stage offsets: TMA bulk (full) or scalar fallback ----
    if (full) {
        if (t == 0) {
            const uint32_t mb = smem_u32(&s_mb);
            asm volatile("mbarrier.arrive.expect_tx.shared.b64 _, [%0], %1;"
                         :: "r"(mb), "r"(GPBK * 600) : "memory");
            asm volatile("cp.async.bulk.shared::cluster.global.mbarrier::complete_tx::bytes "
                         "[%0], [%1], %2, [%3];"
                         :: "r"(smem_u32(s_off)), "l"(off + (size_t)g0 * 150),
                            "r"(GPBK * 600), "r"(mb) : "memory");
        }
        mbar_wait0(smem_u32(&s_mb));
    } else {
        const float* src = off + (size_t)g0 * 150;
        for (int i = t; i < NT * 6; i += THREADS) s_off[i] = src[i];
        __syncthreads();
    }

    // ---- phase 1: per-node local matrix -> fused row [L0..8, ox,oy,oz] ----
    if (t < NT) {
        const int i = t - 25 * (t / 25);
        const float2* o2 = (const float2*)(s_off + t * 6);   // 24B-aligned
        const float2 oA = o2[0], oB = o2[1], oC = o2[2];
        const float4 ax = s_ax[i];
        const float th = x[(size_t)g0 * NN + t] * ax.w;      // coalesced LDG
        const float ox = oA.x, oy = oA.y, oz = oB.x;

        float sx,cx,sy,cy,sz,cz,st,ct;
        __sincosf(oB.y, &sx, &cx);
        __sincosf(oC.x, &sy, &cy);
        __sincosf(oC.y, &sz, &cz);
        __sincosf(th,  &st, &ct);

        const float e00=cz*cy,            e10=sz*cy,            e20=-sy;
        const float e01=cz*sy*sx - sz*cx, e11=sz*sy*sx + cz*cx, e21=cy*sx;
        const float e02=cz*sy*cx + sz*sx, e12=sz*sy*cx - cz*sx, e22=cy*cx;

        const float v=1.f-ct, n1=ax.x, n2=ax.y, n3=ax.z;
        const float n12v=n1*n2*v, n13v=n1*n3*v, n23v=n2*n3*v;
        const float r00=ct+n1*n1*v, r01=n12v-n3*st, r02=n13v+n2*st;
        const float r10=n12v+n3*st, r11=ct+n2*n2*v, r12=n23v-n1*st;
        const float r20=n13v-n2*st, r21=n23v+n1*st, r22=ct+n3*n3*v;

        float4 A, B, C;
        A.x=e00*r00+e01*r10+e02*r20; A.y=e00*r01+e01*r11+e02*r21; A.z=e00*r02+e01*r12+e02*r22;
        A.w=e10*r00+e11*r10+e12*r20; B.x=e10*r01+e11*r11+e12*r21; B.y=e10*r02+e11*r12+e12*r22;
        B.z=e20*r00+e21*r10+e22*r20; B.w=e20*r01+e21*r11+e22*r21; C.x=e20*r02+e21*r12+e22*r22;
        C.y=ox; C.z=oy; C.w=oz;

        float4* row = (float4*)(s_L + t * LW);
        row[0] = A; row[1] = B; row[2] = C;
    }
    __syncthreads();   // inputs consumed; output regions (incl. alias) now writable

    // From here, only warps 0..9 (threads 0..319) participate (full blocks).
    if (full && t >= 320) return;

    // ---- phase 2a (single phase): nodes 1..6 as independent <=2-step chains ----
    if (t < 6 * GPBK) {                                 // 96 threads
        const int g = t / 6, j = t - g * 6, node = 1 + j;
        if (g < ng) {
            const float* Lg = s_L + g * GROW;
            A9 W = load_row(Lg);                      // (L0 | xyz0)
            const float rx = W.p[0], ry = W.p[1], rz = W.p[2];
            W.p[0] = 0.f; W.p[1] = 0.f; W.p[2] = 0.f; // W0 = (L0, 0)
            if (j < 2) {
                step(W, Lg + node * LW);
            } else {
                const int par = 1 + ((node - 3) >> 1);
                step(W, Lg + par * LW);
                step(W, Lg + node * LW);
                store_w(s_W + (g*4 + node-3) * LW, W);
            }
            stage_out(g*NN + node, W, rx, ry, rz, s_pos, s_gps, s_rot);
        }
    }
    if (full) { asm volatile("bar.sync 1, 320;" ::: "memory"); }
    else      { __syncthreads(); }

    // ---- phase 2b: short walks from level-2 ancestors + root staging ----
    if (t < 160) {                       // depth-4 leaves 15..24: 2 steps (5 warps)
        const int g = t / 10, j = t - g * 10, node = 15 + j;
        const int anc3 = 7 + (j >> 1), anc2 = 3 + (j >> 2);
        if (g < ng) {
            const float* Lg = s_L + g * GROW;
            A9 W = load_row(s_W + (g*4 + anc2-3) * LW);
            step(W, Lg + anc3 * LW);
            step(W, Lg + node * LW);
            stage_out(g*NN + node, W, Lg[9], Lg[10], Lg[11], s_pos, s_gps, s_rot);
        }
    } else if (t < 288) {                // depth-3 nodes 7..14: 1 step (4 warps)
        const int i = t - 160, g = i >> 3, j = i & 7, node = 7 + j, par = 3 + (j >> 1);
        if (g < ng) {
            const float* Lg = s_L + g * GROW;
            A9 W = load_row(s_W + (g*4 + par-3) * LW);
            step(W, Lg + node * LW);
            stage_out(g*NN + node, W, Lg[9], Lg[10], Lg[11], s_pos, s_gps, s_rot);
        }
    } else if (t < 288 + GPBK) {         // root outputs (half warp)
        const int g = t - 288;
        if (g < ng) {
            const float* Lg = s_L + g * GROW;
            A9 W = load_row(Lg);
            const float rx = W.p[0], ry = W.p[1], rz = W.p[2];
            W.p[0] = 0.f; W.p[1] = 0.f; W.p[2] = 0.f;
            stage_out(g*NN, W, rx, ry, rz, s_pos, s_gps, s_rot);
        }
    }
    if (full) { asm volatile("bar.sync 1, 320;" ::: "memory"); }
    else      { __syncthreads(); }

    // ---- flush: TMA bulk stores (full) or scalar fallback ----
    if (full) {
        if (t == 0) {
            asm volatile("fence.proxy.async.shared::cta;" ::: "memory");
            asm volatile("cp.async.bulk.global.shared::cta.bulk_group [%0], [%1], %2;"
                         :: "l"(out_pos + (size_t)g0 * 75), "r"(smem_u32(s_pos)),
                            "r"(GPBK * 300) : "memory");
            asm volatile("cp.async.bulk.global.shared::cta.bulk_group [%0], [%1], %2;"
                         :: "l"(out_gpos + (size_t)g0 * 75), "r"(smem_u32(s_gps)),
                            "r"(GPBK * 300) : "memory");
            asm volatile("cp.async.bulk.global.shared::cta.bulk_group [%0], [%1], %2;"
                         :: "l"(out_rot + (size_t)g0 * 225), "r"(smem_u32(s_rot)),
                            "r"(GPBK * 900) : "memory");
            asm volatile("cp.async.bulk.commit_group;" ::: "memory");
            asm volatile("cp.async.bulk.wait_group 0;" ::: "memory");
        }
    } else {
        float* dp = out_pos  + (size_t)g0 * 75;
        float* dg = out_gpos + (size_t)g0 * 75;
        float* dr = out_rot  + (size_t)g0 * 225;
        for (int idx = t; idx < NT * 3; idx += THREADS) { dp[idx] = s_pos[idx]; dg[idx] = s_gps[idx]; }
        for (int idx = t; idx < NT * 9; idx += THREADS) dr[idx] = s_rot[idx];
    }
}

extern "C" void kernel_launch(void* const* d_in, const int* in_sizes, int n_in,
                              void* d_out, int out_size)
{
    const float* x = (const float*)d_in[0];
    const int gn = in_sizes[0];          // G * 25
    const int G  = gn / NN;

    const float* off = nullptr;
    const float* axis = nullptr;
    for (int i = 1; i < n_in; i++) {
        if (in_sizes[i] == 6 * gn) off = (const float*)d_in[i];
        else if (in_sizes[i] == 3 * gn && axis == nullptr) axis = (const float*)d_in[i];
    }

    float* out = (float*)d_out;
    float* out_pos  = out;                    // G*N*3
    float* out_rot  = out + (size_t)gn * 3;   // G*N*9
    float* out_gpos = out + (size_t)gn * 12;  // G*N*3
    (void)out_size;

    const int blocks = (G + GPBK - 1) / GPBK;
    fk_kernel<<<blocks, THREADS>>>(x, off, axis, out_pos, out_rot, out_gpos, G);
}

// round 17
// speedup vs baseline: 1.1171x; 1.1171x over previous
#include <cuda_runtime.h>
#include <cstdint>

#define NN     25
#define GPBK   16              // graphs per tile
#define THREADS 448            // 400 compute threads in phase 1
#define LW     12              // fused row: [L0..8 | x,y,z]; 48B, 16B-aligned
#define GROW   (NN * LW)       // 300 floats per graph in s_L
#define MAXB   608             // 152 SMs * 4 blocks/SM

struct A9 { float R[9]; float p[3]; };

__device__ __forceinline__ uint32_t smem_u32(const void* p) {
    return (uint32_t)__cvta_generic_to_shared(p);
}

__device__ __forceinline__ A9 load_row(const float* __restrict__ row) {
    const float4* rp = (const float4*)row;
    const float4 a = rp[0], b = rp[1], c = rp[2];
    A9 o;
    o.R[0]=a.x; o.R[1]=a.y; o.R[2]=a.z; o.R[3]=a.w; o.R[4]=b.x; o.R[5]=b.y;
    o.R[6]=b.z; o.R[7]=b.w; o.R[8]=c.x; o.p[0]=c.y; o.p[1]=c.z; o.p[2]=c.w;
    return o;
}

// W = W ∘ (L, xyz):  p += R*xyz ; R = R*L
__device__ __forceinline__ void step(A9& W, const float* __restrict__ Lrow) {
    const float4* lp = (const float4*)Lrow;
    const float4 LA = lp[0], LB = lp[1], LC = lp[2];
    W.p[0] += W.R[0]*LC.y + W.R[1]*LC.z + W.R[2]*LC.w;
    W.p[1] += W.R[3]*LC.y + W.R[4]*LC.z + W.R[5]*LC.w;
    W.p[2] += W.R[6]*LC.y + W.R[7]*LC.z + W.R[8]*LC.w;
    const float n0 = W.R[0]*LA.x + W.R[1]*LA.w + W.R[2]*LB.z;
    const float n1 = W.R[0]*LA.y + W.R[1]*LB.x + W.R[2]*LB.w;
    const float n2 = W.R[0]*LA.z + W.R[1]*LB.y + W.R[2]*LC.x;
    const float n3 = W.R[3]*LA.x + W.R[4]*LA.w + W.R[5]*LB.z;
    const float n4 = W.R[3]*LA.y + W.R[4]*LB.x + W.R[5]*LB.w;
    const float n5 = W.R[3]*LA.z + W.R[4]*LB.y + W.R[5]*LC.x;
    const float n6 = W.R[6]*LA.x + W.R[7]*LA.w + W.R[8]*LB.z;
    const float n7 = W.R[6]*LA.y + W.R[7]*LB.x + W.R[8]*LB.w;
    const float n8 = W.R[6]*LA.z + W.R[7]*LB.y + W.R[8]*LC.x;
    W.R[0]=n0; W.R[1]=n1; W.R[2]=n2; W.R[3]=n3; W.R[4]=n4;
    W.R[5]=n5; W.R[6]=n6; W.R[7]=n7; W.R[8]=n8;
}

__device__ __forceinline__ void store_w(float* __restrict__ row, const A9& W) {
    float4* rp = (float4*)row;
    rp[0] = make_float4(W.R[0], W.R[1], W.R[2], W.R[3]);
    rp[1] = make_float4(W.R[4], W.R[5], W.R[6], W.R[7]);
    rp[2] = make_float4(W.R[8], W.p[0], W.p[1], W.p[2]);
}

__device__ __forceinline__ void stage_out(int r, const A9& W,
    float rx, float ry, float rz,
    float* __restrict__ s_pos, float* __restrict__ s_gps, float* __restrict__ s_rot)
{
    float* sp = s_pos + r*3;
    float* sg = s_gps + r*3;
    float* sr = s_rot + r*9;
    sp[0]=W.p[0]; sp[1]=W.p[1]; sp[2]=W.p[2];
    sg[0]=W.p[0]+rx; sg[1]=W.p[1]+ry; sg[2]=W.p[2]+rz;
    #pragma unroll
    for (int k=0;k<9;k++) sr[k]=W.R[k];
}

__device__ __forceinline__ void mbar_wait(uint32_t mb, uint32_t par) {
    uint32_t done;
    do {
        asm volatile(
            "{\n\t.reg .pred p;\n\t"
            "mbarrier.try_wait.parity.acquire.cta.shared::cta.b64 p, [%1], %2, 0x989680;\n\t"
            "selp.b32 %0, 1, 0, p;\n\t}"
            : "=r"(done) : "r"(mb), "r"(par) : "memory");
    } while (!done);
}

__global__ void __launch_bounds__(THREADS, 4)
fk_kernel(const float* __restrict__ x,
          const float* __restrict__ off,
          const float* __restrict__ axis,
          float* __restrict__ out_pos,
          float* __restrict__ out_rot,
          float* __restrict__ out_gpos,
          int G, int numTiles)
{
    __shared__ __align__(16) float s_off[GPBK * NN * 6];   // 9600B
    __shared__ __align__(16) float s_x  [GPBK * NN];       // 1600B
    __shared__ __align__(16) float s_L  [GPBK * GROW];     // 19200B
    __shared__ __align__(16) float s_pos[GPBK * NN * 3];   // 4800B
    __shared__ __align__(16) float s_gps[GPBK * NN * 3];   // 4800B
    __shared__ __align__(16) float s_rot[GPBK * NN * 9];   // 14400B
    __shared__ __align__(16) float s_W  [GPBK * 4 * LW];   // 3072B (nodes 3..6)
    __shared__ float4 s_ax[NN];
    __shared__ __align__(8) unsigned long long s_mb;

    const int t = threadIdx.x;
    const uint32_t mb = smem_u32(&s_mb);

    if (t == 0)
        asm volatile("mbarrier.init.shared.b64 [%0], %1;" :: "r"(mb), "r"(1) : "memory");
    if (t < NN) {
        const float a0 = axis[t*3+0], a1 = axis[t*3+1], a2 = axis[t*3+2];
        s_ax[t] = make_float4(a0, a1, a2, sqrtf(a0*a0 + a1*a1 + a2*a2));
    }
    __syncthreads();

    int tile = blockIdx.x;
    // prologue: issue TMA-in for first tile if full
    if (t == 0 && tile < numTiles && G - tile * GPBK >= GPBK) {
        const size_t g0 = (size_t)tile * GPBK;
        asm volatile("mbarrier.arrive.expect_tx.shared.b64 _, [%0], %1;"
                     :: "r"(mb), "r"(GPBK * 600 + GPBK * 100) : "memory");
        asm volatile("cp.async.bulk.shared::cluster.global.mbarrier::complete_tx::bytes "
                     "[%0], [%1], %2, [%3];"
                     :: "r"(smem_u32(s_off)), "l"(off + g0 * 150),
                        "r"(GPBK * 600), "r"(mb) : "memory");
        asm volatile("cp.async.bulk.shared::cluster.global.mbarrier::complete_tx::bytes "
                     "[%0], [%1], %2, [%3];"
                     :: "r"(smem_u32(s_x)), "l"(x + g0 * NN),
                        "r"(GPBK * 100), "r"(mb) : "memory");
    }
    uint32_t par = 0;

    for (; tile < numTiles; tile += gridDim.x) {
        const size_t g0 = (size_t)tile * GPBK;
        const int ng = min(GPBK, G - tile * GPBK);
        const int NT = ng * NN;
        const bool full = (ng == GPBK);

        // ---- input ready ----
        if (full) {
            mbar_wait(mb, par);
            par ^= 1u;
        } else {
            const float* src = off + g0 * 150;
            for (int i = t; i < NT * 6; i += THREADS) s_off[i] = src[i];
            for (int i = t; i < NT; i += THREADS) s_x[i] = x[g0 * NN + i];
            __syncthreads();
        }

        // ---- phase 1: per-node local matrix -> fused row [L0..8, ox,oy,oz] ----
        if (t < NT) {
            const int i = t - 25 * (t / 25);
            const float2* o2 = (const float2*)(s_off + t * 6);   // 24B-aligned
            const float2 oA = o2[0], oB = o2[1], oC = o2[2];
            const float4 ax = s_ax[i];
            const float th = s_x[t] * ax.w;
            const float ox = oA.x, oy = oA.y, oz = oB.x;

            float sx,cx,sy,cy,sz,cz,st,ct;
            __sincosf(oB.y, &sx, &cx);
            __sincosf(oC.x, &sy, &cy);
            __sincosf(oC.y, &sz, &cz);
            __sincosf(th,  &st, &ct);

            const float e00=cz*cy,            e10=sz*cy,            e20=-sy;
            const float e01=cz*sy*sx - sz*cx, e11=sz*sy*sx + cz*cx, e21=cy*sx;
            const float e02=cz*sy*cx + sz*sx, e12=sz*sy*cx - cz*sx, e22=cy*cx;

            const float v=1.f-ct, n1=ax.x, n2=ax.y, n3=ax.z;
            const float n12v=n1*n2*v, n13v=n1*n3*v, n23v=n2*n3*v;
            const float r00=ct+n1*n1*v, r01=n12v-n3*st, r02=n13v+n2*st;
            const float r10=n12v+n3*st, r11=ct+n2*n2*v, r12=n23v-n1*st;
            const float r20=n13v-n2*st, r21=n23v+n1*st, r22=ct+n3*n3*v;

            float4 A, B, C;
            A.x=e00*r00+e01*r10+e02*r20; A.y=e00*r01+e01*r11+e02*r21; A.z=e00*r02+e01*r12+e02*r22;
            A.w=e10*r00+e11*r10+e12*r20; B.x=e10*r01+e11*r11+e12*r21; B.y=e10*r02+e11*r12+e12*r22;
            B.z=e20*r00+e21*r10+e22*r20; B.w=e20*r01+e21*r11+e22*r21; C.x=e20*r02+e21*r12+e22*r22;
            C.y=ox; C.z=oy; C.w=oz;

            float4* row = (float4*)(s_L + t * LW);
            row[0] = A; row[1] = B; row[2] = C;
        }
        __syncthreads();   // s_off/s_x consumed; s_L ready

        // ---- pipeline service: issue next tile's TMA-in; drain prior TMA-out ----
        if (t == 0) {
            const int nxt = tile + gridDim.x;
            if (nxt < numTiles && G - nxt * GPBK >= GPBK) {
                const size_t ng0 = (size_t)nxt * GPBK;
                asm volatile("mbarrier.arrive.expect_tx.shared.b64 _, [%0], %1;"
                             :: "r"(mb), "r"(GPBK * 600 + GPBK * 100) : "memory");
                asm volatile("cp.async.bulk.shared::cluster.global.mbarrier::complete_tx::bytes "
                             "[%0], [%1], %2, [%3];"
                             :: "r"(smem_u32(s_off)), "l"(off + ng0 * 150),
                                "r"(GPBK * 600), "r"(mb) : "memory");
                asm volatile("cp.async.bulk.shared::cluster.global.mbarrier::complete_tx::bytes "
                             "[%0], [%1], %2, [%3];"
                             :: "r"(smem_u32(s_x)), "l"(x + ng0 * NN),
                                "r"(GPBK * 100), "r"(mb) : "memory");
            }
            // prior tile's bulk stores must finish before s_out is overwritten
            asm volatile("cp.async.bulk.wait_group 0;" ::: "memory");
        }
        __syncthreads();

        // ---- phase 2a level 1: nodes 1,2 ----
        if (t < 2 * GPBK) {
            const int g = t >> 1, node = 1 + (t & 1);
            if (g < ng) {
                const float* Lg = s_L + g * GROW;
                A9 W = load_row(Lg);
                const float rx = W.p[0], ry = W.p[1], rz = W.p[2];
                W.p[0] = 0.f; W.p[1] = 0.f; W.p[2] = 0.f;
                step(W, Lg + node * LW);
                if (node == 1) store_w(s_W + (g*4 + 0) * 0 + 0, W);  // placeholder no-op? no
                stage_out(g*NN + node, W, rx, ry, rz, s_pos, s_gps, s_rot);
                // store W for nodes 1,2 into s_W tail? not needed: level2 recomputes from here
                store_w(s_W + (g*4 + (node-1)) * LW, W);   // temp slots 0,1 hold W1,W2
            }
        }
        __syncthreads();

        // ---- phase 2a level 2: nodes 3..6 (reads W1/W2 from temp slots 0,1) ----
        if (t < 4 * GPBK) {
            const int g = t >> 2, j = t & 3, node = 3 + j, par_n = 1 + (j >> 1);
            if (g < ng) {
                const float* Lg = s_L + g * GROW;
                A9 W = load_row(s_W + (g*4 + (par_n-1)) * LW);   // W1 or W2
                step(W, Lg + node * LW);
                stage_out(g*NN + node, W, Lg[9], Lg[10], Lg[11], s_pos, s_gps, s_rot);
                s_mbW: ;
                // defer writing node's W until after all reads of slots 0,1? slots 2,3 are free:
                if (j >= 2) store_w(s_W + (g*4 + j) * LW, W);    // nodes 5,6 -> slots 2,3
            }
        }
        __syncthreads();

        // ---- phase 2a level 2 fixup: nodes 3,4 W overwrite slots 0,1 ----
        if (t < 2 * GPBK) {
            const int g = t >> 1, j = t & 1, node = 3 + j;       // nodes 3,4
            if (g < ng) {
                const float* Lg = s_L + g * GROW;
                A9 W = load_row(s_W + (g*4 + 0) * LW * 0 + (g*4 + 0) * LW); // W1 (slot 0)
                step(W, Lg + node * LW);
                store_w(s_W + (g*4 + j) * LW, W);                // slots 0,1 = W3,W4
            }
        }
        __syncthreads();

        // ---- phase 2b: short walks from level-2 ancestors + root staging ----
        // s_W layout now: slot0=W3, slot1=W4, slot2=W5, slot3=W6
        if (t < 160) {                       // depth-4 leaves 15..24: 2 steps
            const int g = t / 10, j = t - g * 10, node = 15 + j;
            const int anc3 = 7 + (j >> 1), anc2s = (j >> 2);     // slot of W(3+j/4)
            if (g < ng) {
                const float* Lg = s_L + g * GROW;
                A9 W = load_row(s_W + (g*4 + anc2s) * LW);
                step(W, Lg + anc3 * LW);
                step(W, Lg + node * LW);
                stage_out(g*NN + node, W, Lg[9], Lg[10], Lg[11], s_pos, s_gps, s_rot);
            }
        } else if (t < 288) {                // depth-3 nodes 7..14: 1 step
            const int i = t - 160, g = i >> 3, j = i & 7, node = 7 + j;
            const int pslot = (j >> 1);                          // slot of W(3+j/2)
            if (g < ng) {
                const float* Lg = s_L + g * GROW;
                A9 W = load_row(s_W + (g*4 + pslot) * LW);
                step(W, Lg + node * LW);
                stage_out(g*NN + node, W, Lg[9], Lg[10], Lg[11], s_pos, s_gps, s_rot);
            }
        } else if (t < 288 + GPBK) {         // root outputs
            const int g = t - 288;
            if (g < ng) {
                const float* Lg = s_L + g * GROW;
                A9 W = load_row(Lg);
                const float rx = W.p[0], ry = W.p[1], rz = W.p[2];
                W.p[0] = 0.f; W.p[1] = 0.f; W.p[2] = 0.f;
                stage_out(g*NN, W, rx, ry, rz, s_pos, s_gps, s_rot);
            }
        }
        __syncthreads();

        // ---- flush: commit TMA-out, DO NOT wait (drained next iteration) ----
        if (full) {
            if (t == 0) {
                asm volatile("fence.proxy.async.shared::cta;" ::: "memory");
                asm volatile("cp.async.bulk.global.shared::cta.bulk_group [%0], [%1], %2;"
                             :: "l"(out_pos + g0 * 75), "r"(smem_u32(s_pos)),
                                "r"(GPBK * 300) : "memory");
                asm volatile("cp.async.bulk.global.shared::cta.bulk_group [%0], [%1], %2;"
                             :: "l"(out_gpos + g0 * 75), "r"(smem_u32(s_gps)),
                                "r"(GPBK * 300) : "memory");
                asm volatile("cp.async.bulk.global.shared::cta.bulk_group [%0], [%1], %2;"
                             :: "l"(out_rot + g0 * 225), "r"(smem_u32(s_rot)),
                                "r"(GPBK * 900) : "memory");
                asm volatile("cp.async.bulk.commit_group;" ::: "memory");
            }
        } else {
            float* dp = out_pos  + g0 * 75;
            float* dg = out_gpos + g0 * 75;
            float* dr = out_rot  + g0 * 225;
            for (int idx = t; idx < NT * 3; idx += THREADS) { dp[idx] = s_pos[idx]; dg[idx] = s_gps[idx]; }
            for (int idx = t; idx < NT * 9; idx += THREADS) dr[idx] = s_rot[idx];
            __syncthreads();
        }
    }

    if (t == 0)
        asm volatile("cp.async.bulk.wait_group 0;" ::: "memory");
}

extern "C" void kernel_launch(void* const* d_in, const int* in_sizes, int n_in,
                              void* d_out, int out_size)
{
    const float* x = (const float*)d_in[0];
    const int gn = in_sizes[0];          // G * 25
    const int G  = gn / NN;

    const float* off = nullptr;
    const float* axis = nullptr;
    for (int i = 1; i < n_in; i++) {
        if (in_sizes[i] == 6 * gn) off = (const float*)d_in[i];
        else if (in_sizes[i] == 3 * gn && axis == nullptr) axis = (const float*)d_in[i];
    }

    float* out = (float*)d_out;
    float* out_pos  = out;                    // G*N*3
    float* out_rot  = out + (size_t)gn * 3;   // G*N*9
    float* out_gpos = out + (size_t)gn * 12;  // G*N*3
    (void)out_size;

    const int numTiles = (G + GPBK - 1) / GPBK;
    const int blocks = numTiles < MAXB ? numTiles : MAXB;
    fk_kernel<<<blocks, THREADS>>>(x, off, axis, out_pos, out_rot, out_gpos, G, numTiles);
}